// round 2
// baseline (speedup 1.0000x reference)
#include <cuda_runtime.h>

#define N_NODES 50000
#define N_EDGES 625000
#define D 128
#define ROWS 8   // nodes per block in the output GEMM kernel

// Scratch (no allocations allowed): edge-sum accumulator + in-degree
__device__ float g_sum[N_NODES * D];
__device__ int   g_deg[N_NODES];

// ---------------------------------------------------------------------------
// Kernel 1: zero the accumulators (d_out is poisoned; g_sum/g_deg persist
// across graph replays so they MUST be re-zeroed every launch).
// ---------------------------------------------------------------------------
__global__ void zero_kernel() {
    int i = blockIdx.x * blockDim.x + threadIdx.x;
    const int total4 = N_NODES * D / 4;  // 1.6M float4
    if (i < total4) {
        reinterpret_cast<float4*>(g_sum)[i] = make_float4(0.f, 0.f, 0.f, 0.f);
    }
    if (i < N_NODES) g_deg[i] = 0;
}

// ---------------------------------------------------------------------------
// Kernel 2: edge scatter. One warp per edge; each lane handles 4 contiguous
// floats (float4 gather + one red.global.add.v4.f32). x (25.6 MB) and g_sum
// (25.6 MB) both fit in L2 (~126 MB), so this should be LTS-bound, not HBM.
// ---------------------------------------------------------------------------
__global__ void __launch_bounds__(256) scatter_kernel(
    const float* __restrict__ x,
    const int*   __restrict__ src,
    const int*   __restrict__ dst)
{
    int warp_global = (blockIdx.x * blockDim.x + threadIdx.x) >> 5;
    int lane        = threadIdx.x & 31;
    int n_warps     = (gridDim.x * blockDim.x) >> 5;

    for (int e = warp_global; e < N_EDGES; e += n_warps) {
        int s = __ldg(&src[e]);
        int d = __ldg(&dst[e]);

        float4 v = reinterpret_cast<const float4*>(x + (size_t)s * D)[lane];
        float* outp = g_sum + (size_t)d * D + lane * 4;

        // Vector reduction (PTX ISA 8.1+, sm_90+): 1 op instead of 4 atomicAdds
        asm volatile("red.global.add.v4.f32 [%0], {%1, %2, %3, %4};"
                     :: "l"(outp), "f"(v.x), "f"(v.y), "f"(v.z), "f"(v.w)
                     : "memory");

        if (lane == 0) atomicAdd(&g_deg[d], 1);
    }
}

// ---------------------------------------------------------------------------
// Kernel 3: out[n,:] = x[n,:] @ W_self + (g_sum[n,:]/max(deg,1)) @ W_neigh + b
// Block = 128 threads (thread j -> output column j), 8 nodes per block.
// x/h rows staged in smem and broadcast; W columns are coalesced LDGs that
// stay hot in L1/L2 (128 KB of W total, reused by every block).
// ---------------------------------------------------------------------------
__global__ void __launch_bounds__(128) out_kernel(
    const float* __restrict__ x,
    const float* __restrict__ Ws,
    const float* __restrict__ Wn,
    const float* __restrict__ b,
    float*       __restrict__ out)
{
    __shared__ float xs[ROWS][D];
    __shared__ float hs[ROWS][D];

    int base = blockIdx.x * ROWS;
    int j    = threadIdx.x;

    // Stage 8 x-rows and 8 h-rows (mean = sum / max(deg,1))
    #pragma unroll
    for (int r = 0; r < ROWS; r++) {
        int n = base + r;
        xs[r][j] = x[(size_t)n * D + j];
        float inv = 1.0f / (float)max(g_deg[n], 1);
        hs[r][j] = g_sum[(size_t)n * D + j] * inv;
    }
    __syncthreads();

    float bj = __ldg(&b[j]);
    float acc[ROWS];
    #pragma unroll
    for (int r = 0; r < ROWS; r++) acc[r] = bj;

    #pragma unroll 8
    for (int k = 0; k < D; k++) {
        float ws = __ldg(&Ws[k * D + j]);
        float wn = __ldg(&Wn[k * D + j]);
        #pragma unroll
        for (int r = 0; r < ROWS; r++) {
            acc[r] += xs[r][k] * ws + hs[r][k] * wn;
        }
    }

    #pragma unroll
    for (int r = 0; r < ROWS; r++) {
        out[(size_t)(base + r) * D + j] = acc[r];
    }
}

// ---------------------------------------------------------------------------
// Launch. Inputs (metadata order): x, src, dst, W_self, W_neigh, b
// ---------------------------------------------------------------------------
extern "C" void kernel_launch(void* const* d_in, const int* in_sizes, int n_in,
                              void* d_out, int out_size)
{
    const float* x   = (const float*)d_in[0];
    const int*   src = (const int*)  d_in[1];
    const int*   dst = (const int*)  d_in[2];
    const float* Ws  = (const float*)d_in[3];
    const float* Wn  = (const float*)d_in[4];
    const float* b   = (const float*)d_in[5];
    float*       out = (float*)d_out;

    // zero: cover 1.6M float4 (and N_NODES ints within same grid)
    zero_kernel<<<(N_NODES * D / 4 + 255) / 256, 256>>>();

    // scatter: one warp per edge, exactly-sized grid with grid-stride guard
    scatter_kernel<<<(N_EDGES * 32 + 255) / 256, 256>>>(x, src, dst);

    // fused mean + dual-GEMM + bias (50000 / 8 = 6250 blocks)
    out_kernel<<<N_NODES / ROWS, 128>>>(x, Ws, Wn, b, out);
}

// round 3
// speedup vs baseline: 1.2559x; 1.2559x over previous
#include <cuda_runtime.h>

#define N_NODES 50000
#define N_EDGES 625000
#define D 128
#define ROWS 8
#define NBLK ((N_NODES + 255) / 256)   // 196 scan blocks

// ---------------------------------------------------------------------------
// Device scratch (no allocations allowed)
// ---------------------------------------------------------------------------
__device__ int   g_cnt[N_NODES];          // histogram / fill cursor
__device__ int   g_offloc[NBLK * 256];    // per-block exclusive scan
__device__ int   g_bsum[NBLK];            // per-block totals
__device__ int   g_bpre[NBLK];            // scanned block totals
__device__ int   g_off[N_NODES + 1];      // CSR row offsets
__device__ int   g_sadj[N_EDGES];         // CSR: src node per in-edge slot
__device__ float g_h[N_NODES * D];        // mean-aggregated neighbor features

// ---------------------------------------------------------------------------
// 1) zero the per-node counters (g_h is fully overwritten by agg_kernel,
//    g_cnt returns to 0 after fill, but re-zero for robustness — it's tiny)
// ---------------------------------------------------------------------------
__global__ void zero_kernel() {
    int i = blockIdx.x * blockDim.x + threadIdx.x;
    if (i < N_NODES) g_cnt[i] = 0;
}

// ---------------------------------------------------------------------------
// 2) in-degree histogram
// ---------------------------------------------------------------------------
__global__ void __launch_bounds__(256) hist_kernel(const int* __restrict__ dst) {
    int e = blockIdx.x * blockDim.x + threadIdx.x;
    if (e < N_EDGES) atomicAdd(&g_cnt[dst[e]], 1);
}

// ---------------------------------------------------------------------------
// 3) exclusive scan of g_cnt -> g_off  (3 tiny kernels)
// ---------------------------------------------------------------------------
__global__ void scan1_kernel() {
    __shared__ int s[256];
    int t = threadIdx.x;
    int i = blockIdx.x * 256 + t;
    int v = (i < N_NODES) ? g_cnt[i] : 0;
    s[t] = v; __syncthreads();
    #pragma unroll
    for (int d = 1; d < 256; d <<= 1) {
        int add = (t >= d) ? s[t - d] : 0;
        __syncthreads();
        s[t] += add; __syncthreads();
    }
    g_offloc[i] = s[t] - v;                        // exclusive within block
    if (t == 255) g_bsum[blockIdx.x] = s[255];     // block total
}

__global__ void scan2_kernel() {
    __shared__ int s[256];
    int t = threadIdx.x;
    int v = (t < NBLK) ? g_bsum[t] : 0;
    s[t] = v; __syncthreads();
    #pragma unroll
    for (int d = 1; d < 256; d <<= 1) {
        int add = (t >= d) ? s[t - d] : 0;
        __syncthreads();
        s[t] += add; __syncthreads();
    }
    if (t < NBLK) g_bpre[t] = s[t] - v;
}

__global__ void scan3_kernel() {
    int i = blockIdx.x * 256 + threadIdx.x;
    if (i < N_NODES) g_off[i] = g_offloc[i] + g_bpre[blockIdx.x];
    if (i == 0)      g_off[N_NODES] = N_EDGES;
}

// ---------------------------------------------------------------------------
// 4) fill CSR: slot = --g_cnt[d]; store the SRC NODE ID directly
//    (removes one dependent load in the gather). g_cnt returns to 0.
// ---------------------------------------------------------------------------
__global__ void __launch_bounds__(256) fill_kernel(
    const int* __restrict__ src, const int* __restrict__ dst)
{
    int e = blockIdx.x * blockDim.x + threadIdx.x;
    if (e >= N_EDGES) return;
    int d = dst[e];
    int p = atomicSub(&g_cnt[d], 1) - 1;
    g_sadj[g_off[d] + p] = src[e];
}

// ---------------------------------------------------------------------------
// 5) aggregate: one warp per node. Lane l accumulates floats [4l,4l+4) of the
//    row in registers; NO atomics, ONE store per row. 2-way unroll for MLP.
//    Mean applied here, so out_kernel reads g_h directly.
// ---------------------------------------------------------------------------
__global__ void __launch_bounds__(256) agg_kernel(const float* __restrict__ x) {
    int v    = (blockIdx.x * blockDim.x + threadIdx.x) >> 5;
    int lane = threadIdx.x & 31;
    if (v >= N_NODES) return;

    int beg = g_off[v];
    int end = g_off[v + 1];

    float4 a0 = make_float4(0.f, 0.f, 0.f, 0.f);
    float4 a1 = make_float4(0.f, 0.f, 0.f, 0.f);

    int i = beg;
    for (; i + 1 < end; i += 2) {
        int s0 = g_sadj[i];
        int s1 = g_sadj[i + 1];
        float4 v0 = reinterpret_cast<const float4*>(x + (size_t)s0 * D)[lane];
        float4 v1 = reinterpret_cast<const float4*>(x + (size_t)s1 * D)[lane];
        a0.x += v0.x; a0.y += v0.y; a0.z += v0.z; a0.w += v0.w;
        a1.x += v1.x; a1.y += v1.y; a1.z += v1.z; a1.w += v1.w;
    }
    if (i < end) {
        int s0 = g_sadj[i];
        float4 v0 = reinterpret_cast<const float4*>(x + (size_t)s0 * D)[lane];
        a0.x += v0.x; a0.y += v0.y; a0.z += v0.z; a0.w += v0.w;
    }

    int deg = end - beg;
    float inv = (deg > 0) ? (1.0f / (float)deg) : 0.0f;   // deg==0 -> h=0
    float4 h;
    h.x = (a0.x + a1.x) * inv;
    h.y = (a0.y + a1.y) * inv;
    h.z = (a0.z + a1.z) * inv;
    h.w = (a0.w + a1.w) * inv;
    reinterpret_cast<float4*>(g_h + (size_t)v * D)[lane] = h;
}

// ---------------------------------------------------------------------------
// 6) out[n,:] = x[n,:] @ W_self + h[n,:] @ W_neigh + b
//    128 threads (thread j -> column j), 8 nodes/block. k unrolled by 4 with
//    lds.128 row fragments: per 4k -> 8 LDG + 16 LDS.128 + 64 FFMA.
// ---------------------------------------------------------------------------
__global__ void __launch_bounds__(128) out_kernel(
    const float* __restrict__ x,
    const float* __restrict__ Ws,
    const float* __restrict__ Wn,
    const float* __restrict__ b,
    float*       __restrict__ out)
{
    __shared__ __align__(16) float xs[ROWS][D];
    __shared__ __align__(16) float hs[ROWS][D];

    int base = blockIdx.x * ROWS;
    int j    = threadIdx.x;

    #pragma unroll
    for (int r = 0; r < ROWS; r++) {
        int n = base + r;
        xs[r][j] = x[(size_t)n * D + j];
        hs[r][j] = g_h[(size_t)n * D + j];
    }
    __syncthreads();

    float bj = __ldg(&b[j]);
    float acc[ROWS];
    #pragma unroll
    for (int r = 0; r < ROWS; r++) acc[r] = bj;

    #pragma unroll 4
    for (int k4 = 0; k4 < D / 4; k4++) {
        int k = k4 * 4;
        float w0 = __ldg(&Ws[(k + 0) * D + j]);
        float w1 = __ldg(&Ws[(k + 1) * D + j]);
        float w2 = __ldg(&Ws[(k + 2) * D + j]);
        float w3 = __ldg(&Ws[(k + 3) * D + j]);
        float n0 = __ldg(&Wn[(k + 0) * D + j]);
        float n1 = __ldg(&Wn[(k + 1) * D + j]);
        float n2 = __ldg(&Wn[(k + 2) * D + j]);
        float n3 = __ldg(&Wn[(k + 3) * D + j]);
        #pragma unroll
        for (int r = 0; r < ROWS; r++) {
            float4 xv = *reinterpret_cast<const float4*>(&xs[r][k]);  // lds.128 broadcast
            float4 hv = *reinterpret_cast<const float4*>(&hs[r][k]);
            acc[r] += xv.x * w0 + hv.x * n0;
            acc[r] += xv.y * w1 + hv.y * n1;
            acc[r] += xv.z * w2 + hv.z * n2;
            acc[r] += xv.w * w3 + hv.w * n3;
        }
    }

    #pragma unroll
    for (int r = 0; r < ROWS; r++) {
        out[(size_t)(base + r) * D + j] = acc[r];
    }
}

// ---------------------------------------------------------------------------
// Launch. Inputs (metadata order): x, src, dst, W_self, W_neigh, b
// ---------------------------------------------------------------------------
extern "C" void kernel_launch(void* const* d_in, const int* in_sizes, int n_in,
                              void* d_out, int out_size)
{
    const float* x   = (const float*)d_in[0];
    const int*   src = (const int*)  d_in[1];
    const int*   dst = (const int*)  d_in[2];
    const float* Ws  = (const float*)d_in[3];
    const float* Wn  = (const float*)d_in[4];
    const float* b   = (const float*)d_in[5];
    float*       out = (float*)d_out;

    zero_kernel<<<NBLK, 256>>>();
    hist_kernel<<<(N_EDGES + 255) / 256, 256>>>(dst);
    scan1_kernel<<<NBLK, 256>>>();
    scan2_kernel<<<1, 256>>>();
    scan3_kernel<<<NBLK, 256>>>();
    fill_kernel<<<(N_EDGES + 255) / 256, 256>>>(src, dst);
    agg_kernel<<<(N_NODES * 32 + 255) / 256, 256>>>(x);
    out_kernel<<<N_NODES / ROWS, 128>>>(x, Ws, Wn, b, out);
}

// round 4
// speedup vs baseline: 2.2258x; 1.7722x over previous
#include <cuda_runtime.h>
#include <cuda_fp16.h>
#include <cstdint>

#define N_NODES 50000
#define N_EDGES 625000
#define D 128
#define NBLK ((N_NODES + 255) / 256)   // 196 scan blocks
#define M_BLK 128
#define OUT_BLOCKS ((N_NODES + M_BLK - 1) / M_BLK)  // 391

// ---------------------------------------------------------------------------
// Device scratch (no allocations allowed)
// ---------------------------------------------------------------------------
__device__ int    g_cnt[N_NODES];          // histogram / fill cursor
__device__ int    g_offloc[NBLK * 256];    // per-block exclusive scan
__device__ int    g_bsum[NBLK];            // per-block totals
__device__ int    g_off[N_NODES + 1];      // CSR row offsets
__device__ int    g_sadj[N_EDGES];         // CSR: src node per in-edge slot
__device__ float  g_h[N_NODES * D];        // mean-aggregated neighbor features
__device__ __half g_Whi[D * 256];          // W^T split-hi: [j][k], k in 0..255
__device__ __half g_Wlo[D * 256];          // W^T split-lo

// ---------------------------------------------------------------------------
// 1) zero per-node counters
// ---------------------------------------------------------------------------
__global__ void zero_kernel() {
    int i = blockIdx.x * blockDim.x + threadIdx.x;
    if (i < N_NODES) g_cnt[i] = 0;
}

// ---------------------------------------------------------------------------
// 2) in-degree histogram
// ---------------------------------------------------------------------------
__global__ void __launch_bounds__(256) hist_kernel(const int* __restrict__ dst) {
    int e = blockIdx.x * blockDim.x + threadIdx.x;
    if (e < N_EDGES) atomicAdd(&g_cnt[dst[e]], 1);
}

// ---------------------------------------------------------------------------
// 3a) per-block exclusive scan
// ---------------------------------------------------------------------------
__global__ void scan1_kernel() {
    __shared__ int s[256];
    int t = threadIdx.x;
    int i = blockIdx.x * 256 + t;
    int v = (i < N_NODES) ? g_cnt[i] : 0;
    s[t] = v; __syncthreads();
    #pragma unroll
    for (int d = 1; d < 256; d <<= 1) {
        int add = (t >= d) ? s[t - d] : 0;
        __syncthreads();
        s[t] += add; __syncthreads();
    }
    g_offloc[i] = s[t] - v;
    if (t == 255) g_bsum[blockIdx.x] = s[255];
}

// ---------------------------------------------------------------------------
// 3b) fused block-prefix + add (replaces old scan2 + scan3)
// ---------------------------------------------------------------------------
__global__ void scan23_kernel() {
    __shared__ int red[256];
    int i = blockIdx.x, t = threadIdx.x;
    int v = (t < i) ? g_bsum[t] : 0;     // NBLK=196 <= 256
    red[t] = v; __syncthreads();
    #pragma unroll
    for (int s = 128; s > 0; s >>= 1) {
        if (t < s) red[t] += red[t + s];
        __syncthreads();
    }
    int prefix = red[0];
    int idx = i * 256 + t;
    if (idx < N_NODES) g_off[idx] = g_offloc[idx] + prefix;
    if (i == 0 && t == 0) g_off[N_NODES] = N_EDGES;
}

// ---------------------------------------------------------------------------
// 4) fill CSR (stores src node ids directly); g_cnt returns to 0
// ---------------------------------------------------------------------------
__global__ void __launch_bounds__(256) fill_kernel(
    const int* __restrict__ src, const int* __restrict__ dst)
{
    int e = blockIdx.x * blockDim.x + threadIdx.x;
    if (e >= N_EDGES) return;
    int d = dst[e];
    int p = atomicSub(&g_cnt[d], 1) - 1;
    g_sadj[g_off[d] + p] = src[e];
}

// ---------------------------------------------------------------------------
// 5) aggregate: one warp per node, no atomics, one store per row
// ---------------------------------------------------------------------------
__global__ void __launch_bounds__(256) agg_kernel(const float* __restrict__ x) {
    int v    = (blockIdx.x * blockDim.x + threadIdx.x) >> 5;
    int lane = threadIdx.x & 31;
    if (v >= N_NODES) return;

    int beg = g_off[v];
    int end = g_off[v + 1];

    float4 a0 = make_float4(0.f, 0.f, 0.f, 0.f);
    float4 a1 = make_float4(0.f, 0.f, 0.f, 0.f);

    int i = beg;
    for (; i + 1 < end; i += 2) {
        int s0 = g_sadj[i];
        int s1 = g_sadj[i + 1];
        float4 v0 = reinterpret_cast<const float4*>(x + (size_t)s0 * D)[lane];
        float4 v1 = reinterpret_cast<const float4*>(x + (size_t)s1 * D)[lane];
        a0.x += v0.x; a0.y += v0.y; a0.z += v0.z; a0.w += v0.w;
        a1.x += v1.x; a1.y += v1.y; a1.z += v1.z; a1.w += v1.w;
    }
    if (i < end) {
        int s0 = g_sadj[i];
        float4 v0 = reinterpret_cast<const float4*>(x + (size_t)s0 * D)[lane];
        a0.x += v0.x; a0.y += v0.y; a0.z += v0.z; a0.w += v0.w;
    }

    int deg = end - beg;
    float inv = (deg > 0) ? (1.0f / (float)deg) : 0.0f;
    float4 h;
    h.x = (a0.x + a1.x) * inv;
    h.y = (a0.y + a1.y) * inv;
    h.z = (a0.z + a1.z) * inv;
    h.w = (a0.w + a1.w) * inv;
    reinterpret_cast<float4*>(g_h + (size_t)v * D)[lane] = h;
}

// ---------------------------------------------------------------------------
// 6a) W conversion: [k][j] fp32 (Ws for k<128, Wn for k>=128) ->
//     transposed [j][k] fp16 hi/lo split
// ---------------------------------------------------------------------------
__global__ void __launch_bounds__(128) wconv_kernel(
    const float* __restrict__ Ws, const float* __restrict__ Wn)
{
    int k = blockIdx.x;       // 0..255
    int j = threadIdx.x;      // 0..127
    float w = (k < D) ? Ws[k * D + j] : Wn[(k - D) * D + j];
    __half hi = __float2half_rn(w);
    __half lo = __float2half_rn(w - __half2float(hi));
    g_Whi[j * 256 + k] = hi;
    g_Wlo[j * 256 + k] = lo;
}

// ---------------------------------------------------------------------------
// 6b) tensor-core GEMM: out = [x | h] @ [Ws; Wn] + b
//     fp16 2-term split (AhBh + AlBh + AhBl), fp32 accumulate.
//     128 rows/block, 4 warps x 32 rows, N=128, K=256 in two 128-chunks.
// ---------------------------------------------------------------------------
#define A_STRIDE 264        // 256 + 8 halves pad (bank-shift 4 words/row)
#define B_STRIDE 136        // 128 + 8 halves pad
#define SM_A_HI  0
#define SM_A_LO  (M_BLK * A_STRIDE)                 // 33792
#define SM_B_HI  (2 * M_BLK * A_STRIDE)             // 67584
#define SM_B_LO  (2 * M_BLK * A_STRIDE + D * B_STRIDE)
#define SMEM_HALVES (2 * M_BLK * A_STRIDE + 2 * D * B_STRIDE)  // 102400
#define SMEM_BYTES  (SMEM_HALVES * 2)                           // 204800

__device__ __forceinline__ void ldsm_x4(uint32_t* r, uint32_t addr) {
    asm volatile("ldmatrix.sync.aligned.m8n8.x4.shared.b16 {%0,%1,%2,%3}, [%4];"
                 : "=r"(r[0]), "=r"(r[1]), "=r"(r[2]), "=r"(r[3]) : "r"(addr));
}
__device__ __forceinline__ void ldsm_x2(uint32_t* r, uint32_t addr) {
    asm volatile("ldmatrix.sync.aligned.m8n8.x2.shared.b16 {%0,%1}, [%2];"
                 : "=r"(r[0]), "=r"(r[1]) : "r"(addr));
}
__device__ __forceinline__ void mma16816(float* c, const uint32_t* a, const uint32_t* b) {
    asm volatile(
        "mma.sync.aligned.m16n8k16.row.col.f32.f16.f16.f32 "
        "{%0,%1,%2,%3}, {%4,%5,%6,%7}, {%8,%9}, {%0,%1,%2,%3};"
        : "+f"(c[0]), "+f"(c[1]), "+f"(c[2]), "+f"(c[3])
        : "r"(a[0]), "r"(a[1]), "r"(a[2]), "r"(a[3]), "r"(b[0]), "r"(b[1]));
}

__global__ void __launch_bounds__(128, 1) out_kernel(
    const float* __restrict__ x,
    const float* __restrict__ b,
    float*       __restrict__ out)
{
    extern __shared__ __half sm[];
    __half* A_hi = sm + SM_A_HI;
    __half* A_lo = sm + SM_A_LO;
    __half* B_hi = sm + SM_B_HI;
    __half* B_lo = sm + SM_B_LO;

    const int t    = threadIdx.x;
    const int warp = t >> 5;
    const int lane = t & 31;
    const int base = blockIdx.x * M_BLK;

    // ---- stage A: 128 rows of [x | h], converted to fp16 hi/lo ----
    {
        int row_off = t >> 6;          // 0/1
        int part    = (t >> 5) & 1;    // 0: x, 1: h
        int l16     = t & 31;          // float4 index within the 128 cols
        const float* src = part ? g_h : x;
        #pragma unroll 4
        for (int it = 0; it < 64; it++) {
            int row  = it * 2 + row_off;
            int node = base + row;
            float4 v = make_float4(0.f, 0.f, 0.f, 0.f);
            if (node < N_NODES)
                v = reinterpret_cast<const float4*>(src + (size_t)node * D)[l16];
            __half h0 = __float2half_rn(v.x);
            __half h1 = __float2half_rn(v.y);
            __half h2 = __float2half_rn(v.z);
            __half h3 = __float2half_rn(v.w);
            __half l0 = __float2half_rn(v.x - __half2float(h0));
            __half l1 = __float2half_rn(v.y - __half2float(h1));
            __half l2 = __float2half_rn(v.z - __half2float(h2));
            __half l3 = __float2half_rn(v.w - __half2float(h3));
            int k   = part * 128 + l16 * 4;
            int off = row * A_STRIDE + k;
            __half2 ph0 = __halves2half2(h0, h1), ph1 = __halves2half2(h2, h3);
            __half2 pl0 = __halves2half2(l0, l1), pl1 = __halves2half2(l2, l3);
            uint2 uh, ul;
            uh.x = *reinterpret_cast<uint32_t*>(&ph0);
            uh.y = *reinterpret_cast<uint32_t*>(&ph1);
            ul.x = *reinterpret_cast<uint32_t*>(&pl0);
            ul.y = *reinterpret_cast<uint32_t*>(&pl1);
            *reinterpret_cast<uint2*>(A_hi + off) = uh;
            *reinterpret_cast<uint2*>(A_lo + off) = ul;
        }
    }

    // ---- accumulators: 2 m-tiles x 16 n-tiles x 4 regs ----
    float c[2][16][4];
    #pragma unroll
    for (int mt = 0; mt < 2; mt++)
        #pragma unroll
        for (int nt = 0; nt < 16; nt++)
            #pragma unroll
            for (int i = 0; i < 4; i++) c[mt][nt][i] = 0.f;

    const int mrow = warp * 32;

    // ldmatrix source row/col offsets (per-lane, constant across loop)
    const int a_r = lane & 15;             // row within 16-row tile
    const int a_k = (lane >> 4) * 8;       // k offset 0/8
    const int b_n = lane & 7;              // n row within 8
    const int b_k = ((lane >> 3) & 1) * 8; // k offset 0/8 (x2 uses lanes 0-15)

    // ---- K loop: 2 chunks of 128 ----
    for (int kc = 0; kc < 2; kc++) {
        // stage B chunk [128 n][128 k] hi+lo
        __syncthreads();
        {
            int kbase = kc * 128;
            #pragma unroll 4
            for (int idx = t; idx < 128 * 16; idx += 128) {
                int n = idx >> 4, q = idx & 15;          // q: uint4 (8 halves)
                const uint4* sh = reinterpret_cast<const uint4*>(g_Whi + n * 256 + kbase) + q;
                const uint4* sl = reinterpret_cast<const uint4*>(g_Wlo + n * 256 + kbase) + q;
                *reinterpret_cast<uint4*>(B_hi + n * B_STRIDE + q * 8) = *sh;
                *reinterpret_cast<uint4*>(B_lo + n * B_STRIDE + q * 8) = *sl;
            }
        }
        __syncthreads();

        #pragma unroll
        for (int kt = 0; kt < 8; kt++) {
            int kg = kc * 128 + kt * 16;   // global k for A
            int kk = kt * 16;              // k within B chunk

            uint32_t ah[2][4], al[2][4];
            #pragma unroll
            for (int mt = 0; mt < 2; mt++) {
                int arow = mrow + mt * 16 + a_r;
                uint32_t addr_h = (uint32_t)__cvta_generic_to_shared(
                    A_hi + arow * A_STRIDE + kg + a_k);
                uint32_t addr_l = (uint32_t)__cvta_generic_to_shared(
                    A_lo + arow * A_STRIDE + kg + a_k);
                ldsm_x4(ah[mt], addr_h);
                ldsm_x4(al[mt], addr_l);
            }

            #pragma unroll
            for (int nt = 0; nt < 16; nt++) {
                uint32_t bh[2], bl[2];
                uint32_t baddr_h = (uint32_t)__cvta_generic_to_shared(
                    B_hi + (nt * 8 + b_n) * B_STRIDE + kk + b_k);
                uint32_t baddr_l = (uint32_t)__cvta_generic_to_shared(
                    B_lo + (nt * 8 + b_n) * B_STRIDE + kk + b_k);
                ldsm_x2(bh, baddr_h);
                ldsm_x2(bl, baddr_l);

                #pragma unroll
                for (int mt = 0; mt < 2; mt++) {
                    mma16816(c[mt][nt], ah[mt], bh);   // AhBh
                    mma16816(c[mt][nt], al[mt], bh);   // AlBh
                    mma16816(c[mt][nt], ah[mt], bl);   // AhBl
                }
            }
        }
    }

    // ---- epilogue: + bias, store fp32 ----
    #pragma unroll
    for (int nt = 0; nt < 16; nt++) {
        int col = nt * 8 + (lane & 3) * 2;
        float2 bv = *reinterpret_cast<const float2*>(b + col);
        #pragma unroll
        for (int mt = 0; mt < 2; mt++) {
            int r0 = base + mrow + mt * 16 + (lane >> 2);
            int r1 = r0 + 8;
            if (r0 < N_NODES) {
                float2 o; o.x = c[mt][nt][0] + bv.x; o.y = c[mt][nt][1] + bv.y;
                *reinterpret_cast<float2*>(out + (size_t)r0 * D + col) = o;
            }
            if (r1 < N_NODES) {
                float2 o; o.x = c[mt][nt][2] + bv.x; o.y = c[mt][nt][3] + bv.y;
                *reinterpret_cast<float2*>(out + (size_t)r1 * D + col) = o;
            }
        }
    }
}

// ---------------------------------------------------------------------------
// Launch. Inputs (metadata order): x, src, dst, W_self, W_neigh, b
// ---------------------------------------------------------------------------
extern "C" void kernel_launch(void* const* d_in, const int* in_sizes, int n_in,
                              void* d_out, int out_size)
{
    const float* x   = (const float*)d_in[0];
    const int*   src = (const int*)  d_in[1];
    const int*   dst = (const int*)  d_in[2];
    const float* Ws  = (const float*)d_in[3];
    const float* Wn  = (const float*)d_in[4];
    const float* b   = (const float*)d_in[5];
    float*       out = (float*)d_out;

    static bool attr_set = false;
    if (!attr_set) {
        cudaFuncSetAttribute(out_kernel,
                             cudaFuncAttributeMaxDynamicSharedMemorySize, SMEM_BYTES);
        attr_set = true;
    }

    zero_kernel<<<NBLK, 256>>>();
    wconv_kernel<<<256, 128>>>(Ws, Wn);
    hist_kernel<<<(N_EDGES + 255) / 256, 256>>>(dst);
    scan1_kernel<<<NBLK, 256>>>();
    scan23_kernel<<<NBLK, 256>>>();
    fill_kernel<<<(N_EDGES + 255) / 256, 256>>>(src, dst);
    agg_kernel<<<(N_NODES * 32 + 255) / 256, 256>>>(x);
    out_kernel<<<OUT_BLOCKS, 128, SMEM_BYTES>>>(x, b, out);
}